// round 1
// baseline (speedup 1.0000x reference)
#include <cuda_runtime.h>
#include <cstdint>

// Problem constants
#define Bsz 4
#define Tsz 4096
#define Isz 2048
#define Esz 16
#define Jsz 128
#define Csz 1024

#define BM 128
#define BN 128
#define BK 32
#define NTHREADS 256
// warp grid: 2 (M) x 4 (N); warp tile 64x32
#define SA_LD (BK + 4)   // 36 u32 per row, conflict-free fragment loads

__device__ __forceinline__ uint32_t f32_to_tf32(float f) {
    uint32_t u;
    asm("cvt.rna.tf32.f32 %0, %1;" : "=r"(u) : "f"(f));
    return u;
}

__device__ __forceinline__ void mma_tf32(float c[4], const uint32_t a[4], const uint32_t b[2]) {
    asm volatile(
        "mma.sync.aligned.m16n8k8.row.col.f32.tf32.tf32.f32 "
        "{%0,%1,%2,%3}, {%4,%5,%6,%7}, {%8,%9}, {%0,%1,%2,%3};\n"
        : "+f"(c[0]), "+f"(c[1]), "+f"(c[2]), "+f"(c[3])
        : "r"(a[0]), "r"(a[1]), "r"(a[2]), "r"(a[3]), "r"(b[0]), "r"(b[1]));
}

__global__ void __launch_bounds__(NTHREADS, 2)
gather_gemm_tf32(const float* __restrict__ X,
                 const void* __restrict__ ind_raw,
                 const float* __restrict__ W,
                 float* __restrict__ out)
{
    __shared__ uint32_t sA[BM][SA_LD];
    __shared__ uint32_t sB[BN][SA_LD];
    __shared__ int sIdx[BM];
    __shared__ int sIs64;

    const int mtile = blockIdx.x;   // 0..7
    const int e     = blockIdx.y;   // 0..15
    const int b     = blockIdx.z;   // 0..3
    const int tid   = threadIdx.x;
    const int lane  = tid & 31;
    const int warp  = tid >> 5;
    const int wm    = warp & 1;     // 0..1
    const int wn    = warp >> 1;    // 0..3

    // ---- dtype sniff: int64 vs int32 indices (values < 4096 -> int64 odd words are 0).
    // First 64 int32 words are in-bounds for both dtypes (65536 elements either way).
    if (warp == 0) {
        const uint32_t* iw = (const uint32_t*)ind_raw;
        uint32_t oddw = iw[2 * lane + 1];
        unsigned mask = __ballot_sync(0xFFFFFFFFu, oddw == 0u);
        if (lane == 0) sIs64 = (mask == 0xFFFFFFFFu) ? 1 : 0;
    }
    __syncthreads();
    const int is64 = sIs64;

    // ---- load gather indices for this tile
    if (tid < BM) {
        size_t p = ((size_t)b * Esz + e) * Csz + (size_t)mtile * BM + tid;
        int t;
        if (is64) t = (int)((const long long*)ind_raw)[p];
        else      t = ((const int*)ind_raw)[p];
        sIdx[tid] = t;
    }
    __syncthreads();

    const float* Xb = X + (size_t)b * Tsz * Isz;
    const float* Wb = W + (size_t)e * Jsz * Isz;

    // global-load assignment: each thread loads 4 rows (stride 32), one float4 per row
    const int mrow = tid >> 3;        // 0..31
    const int k4   = (tid & 7) * 4;   // float col within BK

    // precompute row base pointers
    const float* aPtr[4];
    const float* bPtr[4];
#pragma unroll
    for (int r = 0; r < 4; r++) {
        int m = mrow + r * 32;
        aPtr[r] = Xb + (size_t)sIdx[m] * Isz + k4;
        bPtr[r] = Wb + (size_t)m * Isz + k4;
    }

    float acc[4][4][4];
#pragma unroll
    for (int i = 0; i < 4; i++)
#pragma unroll
        for (int j = 0; j < 4; j++)
#pragma unroll
            for (int r = 0; r < 4; r++) acc[i][j][r] = 0.0f;

    const int g = lane >> 2;   // 0..7
    const int q = lane & 3;    // 0..3

    for (int k0 = 0; k0 < Isz; k0 += BK) {
        // ---- global -> smem (convert to tf32 bit patterns on the way in)
#pragma unroll
        for (int r = 0; r < 4; r++) {
            int m = mrow + r * 32;
            float4 va = *(const float4*)(aPtr[r] + k0);
            float4 vb = *(const float4*)(bPtr[r] + k0);
            uint4 ua = make_uint4(f32_to_tf32(va.x), f32_to_tf32(va.y),
                                  f32_to_tf32(va.z), f32_to_tf32(va.w));
            uint4 ub = make_uint4(f32_to_tf32(vb.x), f32_to_tf32(vb.y),
                                  f32_to_tf32(vb.z), f32_to_tf32(vb.w));
            *(uint4*)&sA[m][k4] = ua;
            *(uint4*)&sB[m][k4] = ub;
        }
        __syncthreads();

        // ---- compute: 4 k8-steps per BK
#pragma unroll
        for (int ks = 0; ks < 4; ks++) {
            const int kk = ks * 8;
            uint32_t areg[4][4];
            uint32_t breg[4][2];
#pragma unroll
            for (int i = 0; i < 4; i++) {
                int m0 = wm * 64 + i * 16;
                areg[i][0] = sA[m0 + g][kk + q];
                areg[i][1] = sA[m0 + g + 8][kk + q];
                areg[i][2] = sA[m0 + g][kk + q + 4];
                areg[i][3] = sA[m0 + g + 8][kk + q + 4];
            }
#pragma unroll
            for (int j = 0; j < 4; j++) {
                int n0 = wn * 32 + j * 8;
                breg[j][0] = sB[n0 + g][kk + q];
                breg[j][1] = sB[n0 + g][kk + q + 4];
            }
#pragma unroll
            for (int i = 0; i < 4; i++)
#pragma unroll
                for (int j = 0; j < 4; j++)
                    mma_tf32(acc[i][j], areg[i], breg[j]);
        }
        __syncthreads();
    }

    // ---- epilogue: out[b][e][c][j], BN == J so cols map directly
    float* outp = out + (((size_t)b * Esz + e) * Csz + (size_t)mtile * BM) * Jsz;
#pragma unroll
    for (int i = 0; i < 4; i++) {
        int row0 = wm * 64 + i * 16 + g;
#pragma unroll
        for (int j = 0; j < 4; j++) {
            int col = wn * 32 + j * 8 + 2 * q;
            float2 v0 = make_float2(acc[i][j][0], acc[i][j][1]);
            float2 v1 = make_float2(acc[i][j][2], acc[i][j][3]);
            *(float2*)(outp + (size_t)row0 * Jsz + col)       = v0;
            *(float2*)(outp + (size_t)(row0 + 8) * Jsz + col) = v1;
        }
    }
}

extern "C" void kernel_launch(void* const* d_in, const int* in_sizes, int n_in,
                              void* d_out, int out_size)
{
    const float* X   = (const float*)d_in[0];
    const void*  ind = (const void*)d_in[1];
    const float* W   = (const float*)d_in[2];
    float* out = (float*)d_out;

    dim3 grid(Csz / BM, Esz, Bsz);   // (8, 16, 4) = 512 CTAs
    dim3 block(NTHREADS);
    gather_gemm_tf32<<<grid, block>>>(X, ind, W, out);
}

// round 2
// speedup vs baseline: 1.0483x; 1.0483x over previous
#include <cuda_runtime.h>
#include <cstdint>

// Problem constants
#define Bsz 4
#define Tsz 4096
#define Isz 2048
#define Esz 16
#define Jsz 128
#define Csz 1024

#define BM 128
#define BN 128
#define BK 32
#define NTHREADS 256
#define STAGES 3
#define PITCH 36                     // floats per row: 32 data + 4 pad (conflict-free frag LDS)
#define TILE_FLOATS (BM * PITCH)     // per A or B tile per stage
#define STAGE_FLOATS (2 * TILE_FLOATS)
#define SMEM_BYTES (STAGES * STAGE_FLOATS * 4)

__device__ __forceinline__ uint32_t f32_to_tf32(float f) {
    uint32_t u;
    asm("cvt.rna.tf32.f32 %0, %1;" : "=r"(u) : "f"(f));
    return u;
}

__device__ __forceinline__ void mma_tf32(float c[4], const uint32_t a[4], const uint32_t b[2]) {
    asm volatile(
        "mma.sync.aligned.m16n8k8.row.col.f32.tf32.tf32.f32 "
        "{%0,%1,%2,%3}, {%4,%5,%6,%7}, {%8,%9}, {%0,%1,%2,%3};\n"
        : "+f"(c[0]), "+f"(c[1]), "+f"(c[2]), "+f"(c[3])
        : "r"(a[0]), "r"(a[1]), "r"(a[2]), "r"(a[3]), "r"(b[0]), "r"(b[1]));
}

__device__ __forceinline__ void cp_async16(uint32_t smem_addr, const void* gptr) {
    asm volatile("cp.async.cg.shared.global [%0], [%1], 16;\n"
                 :: "r"(smem_addr), "l"(gptr));
}
__device__ __forceinline__ void cp_commit() {
    asm volatile("cp.async.commit_group;\n" ::: "memory");
}
template <int N>
__device__ __forceinline__ void cp_wait() {
    asm volatile("cp.async.wait_group %0;\n" :: "n"(N) : "memory");
}

__global__ void __launch_bounds__(NTHREADS, 2)
gather_gemm_tf32(const float* __restrict__ X,
                 const void* __restrict__ ind_raw,
                 const float* __restrict__ W,
                 float* __restrict__ out)
{
    extern __shared__ float smem[];   // [STAGES][2][BM][PITCH]
    __shared__ int sIdx[BM];
    __shared__ int sIs64;

    const int mtile = blockIdx.x;   // 0..7
    const int e     = blockIdx.y;   // 0..15
    const int b     = blockIdx.z;   // 0..3
    const int tid   = threadIdx.x;
    const int lane  = tid & 31;
    const int warp  = tid >> 5;
    const int wm    = warp & 1;     // 0..1
    const int wn    = warp >> 1;    // 0..3

    // ---- dtype sniff: int64 vs int32 indices (values < 4096 -> int64 odd words zero).
    if (warp == 0) {
        const uint32_t* iw = (const uint32_t*)ind_raw;
        uint32_t oddw = iw[2 * lane + 1];
        unsigned mask = __ballot_sync(0xFFFFFFFFu, oddw == 0u);
        if (lane == 0) sIs64 = (mask == 0xFFFFFFFFu) ? 1 : 0;
    }
    __syncthreads();
    const int is64 = sIs64;

    if (tid < BM) {
        size_t p = ((size_t)b * Esz + e) * Csz + (size_t)mtile * BM + tid;
        int t;
        if (is64) t = (int)((const long long*)ind_raw)[p];
        else      t = ((const int*)ind_raw)[p];
        sIdx[tid] = t;
    }
    __syncthreads();

    const float* Xb = X + (size_t)b * Tsz * Isz;
    const float* Wb = W + (size_t)e * Jsz * Isz;

    // global-load assignment: each thread loads 4 rows (stride 32), one float4 per row
    const int mrow = tid >> 3;        // 0..31
    const int k4   = (tid & 7) * 4;   // float col within BK

    const float* aPtr[4];
    const float* bPtr[4];
#pragma unroll
    for (int r = 0; r < 4; r++) {
        int m = mrow + r * 32;
        aPtr[r] = Xb + (size_t)sIdx[m] * Isz + k4;
        bPtr[r] = Wb + (size_t)m * Isz + k4;
    }

    // smem byte addresses for this thread's cp.async destinations (per stage)
    uint32_t smemBase = (uint32_t)__cvta_generic_to_shared(smem);
    uint32_t dstA[4], dstB[4];
#pragma unroll
    for (int r = 0; r < 4; r++) {
        int m = mrow + r * 32;
        dstA[r] = smemBase + (uint32_t)((m * PITCH + k4) * 4);
        dstB[r] = smemBase + (uint32_t)((TILE_FLOATS + m * PITCH + k4) * 4);
    }

    float acc[4][4][4];
#pragma unroll
    for (int i = 0; i < 4; i++)
#pragma unroll
        for (int j = 0; j < 4; j++)
#pragma unroll
            for (int r = 0; r < 4; r++) acc[i][j][r] = 0.0f;

    const int g = lane >> 2;   // 0..7
    const int q = lane & 3;    // 0..3

    const int NITER = Isz / BK;   // 64

    // ---- prologue: issue stages 0 and 1
#pragma unroll
    for (int s = 0; s < 2; s++) {
        uint32_t off = (uint32_t)(s * STAGE_FLOATS * 4);
        int k0 = s * BK;
#pragma unroll
        for (int r = 0; r < 4; r++) {
            cp_async16(dstA[r] + off, aPtr[r] + k0);
            cp_async16(dstB[r] + off, bPtr[r] + k0);
        }
        cp_commit();
    }

    int sc = 0;          // stage being computed
    int si = 2;          // stage being issued
    for (int it = 0; it < NITER; it++) {
        cp_wait<1>();
        __syncthreads();

        // issue stage it+2 (overwrites buffer consumed at it-1; barrier above protects it)
        if (it + 2 < NITER) {
            uint32_t off = (uint32_t)(si * STAGE_FLOATS * 4);
            int k0 = (it + 2) * BK;
#pragma unroll
            for (int r = 0; r < 4; r++) {
                cp_async16(dstA[r] + off, aPtr[r] + k0);
                cp_async16(dstB[r] + off, bPtr[r] + k0);
            }
            cp_commit();
        }

        const float* cA = smem + sc * STAGE_FLOATS;
        const float* cB = cA + TILE_FLOATS;

#pragma unroll
        for (int ks = 0; ks < 4; ks++) {
            const int kk = ks * 8;
            uint32_t areg[4][4];
            uint32_t breg[4][2];
#pragma unroll
            for (int i = 0; i < 4; i++) {
                int m0 = wm * 64 + i * 16;
                areg[i][0] = f32_to_tf32(cA[(m0 + g)     * PITCH + kk + q]);
                areg[i][1] = f32_to_tf32(cA[(m0 + g + 8) * PITCH + kk + q]);
                areg[i][2] = f32_to_tf32(cA[(m0 + g)     * PITCH + kk + q + 4]);
                areg[i][3] = f32_to_tf32(cA[(m0 + g + 8) * PITCH + kk + q + 4]);
            }
#pragma unroll
            for (int j = 0; j < 4; j++) {
                int n0 = wn * 32 + j * 8;
                breg[j][0] = f32_to_tf32(cB[(n0 + g) * PITCH + kk + q]);
                breg[j][1] = f32_to_tf32(cB[(n0 + g) * PITCH + kk + q + 4]);
            }
#pragma unroll
            for (int i = 0; i < 4; i++)
#pragma unroll
                for (int j = 0; j < 4; j++)
                    mma_tf32(acc[i][j], areg[i], breg[j]);
        }

        if (++sc == STAGES) sc = 0;
        if (++si == STAGES) si = 0;
    }

    // ---- epilogue: out[b][e][c][j], BN == J so cols map directly
    float* outp = out + (((size_t)b * Esz + e) * Csz + (size_t)mtile * BM) * Jsz;
#pragma unroll
    for (int i = 0; i < 4; i++) {
        int row0 = wm * 64 + i * 16 + g;
#pragma unroll
        for (int j = 0; j < 4; j++) {
            int col = wn * 32 + j * 8 + 2 * q;
            float2 v0 = make_float2(acc[i][j][0], acc[i][j][1]);
            float2 v1 = make_float2(acc[i][j][2], acc[i][j][3]);
            *(float2*)(outp + (size_t)row0 * Jsz + col)       = v0;
            *(float2*)(outp + (size_t)(row0 + 8) * Jsz + col) = v1;
        }
    }
}

extern "C" void kernel_launch(void* const* d_in, const int* in_sizes, int n_in,
                              void* d_out, int out_size)
{
    const float* X   = (const float*)d_in[0];
    const void*  ind = (const void*)d_in[1];
    const float* W   = (const float*)d_in[2];
    float* out = (float*)d_out;

    cudaFuncSetAttribute(gather_gemm_tf32,
                         cudaFuncAttributeMaxDynamicSharedMemorySize, SMEM_BYTES);

    dim3 grid(Csz / BM, Esz, Bsz);   // (8, 16, 4) = 512 CTAs
    dim3 block(NTHREADS);
    gather_gemm_tf32<<<grid, block, SMEM_BYTES>>>(X, ind, W, out);
}

// round 4
// speedup vs baseline: 1.2392x; 1.1821x over previous
#include <cuda_runtime.h>
#include <cstdint>

// Problem constants
#define Bsz 4
#define Tsz 4096
#define Isz 2048
#define Esz 16
#define Jsz 128
#define Csz 1024

#define BM 128
#define BN 128
#define BK 32
#define NTHREADS 128            // 4 warps: 2 (M) x 2 (N), warp tile 64x64
#define NITER (Isz / BK)        // 64
#define PITCH 36                // u32 per row: 32 data + 4 pad (conflict-free)
#define TILE_FLOATS (BM * PITCH)
#define STAGE_FLOATS (2 * TILE_FLOATS)
#define DYN_SMEM (2 * STAGE_FLOATS * 4)   // 73728 B

__device__ __forceinline__ uint32_t f32_to_tf32(float f) {
    uint32_t u;
    asm("cvt.rna.tf32.f32 %0, %1;" : "=r"(u) : "f"(f));
    return u;
}

__device__ __forceinline__ void sts_tf32x4(uint32_t* addr, float4 v) {
    uint32_t x = f32_to_tf32(v.x), y = f32_to_tf32(v.y),
             z = f32_to_tf32(v.z), w = f32_to_tf32(v.w);
    asm volatile("st.shared.v4.b32 [%0], {%1,%2,%3,%4};"
                 :: "l"(addr), "r"(x), "r"(y), "r"(z), "r"(w) : "memory");
}

__device__ __forceinline__ void mma_tf32(float c[4], const uint32_t a[4], const uint32_t b[2]) {
    asm volatile(
        "mma.sync.aligned.m16n8k8.row.col.f32.tf32.tf32.f32 "
        "{%0,%1,%2,%3}, {%4,%5,%6,%7}, {%8,%9}, {%0,%1,%2,%3};\n"
        : "+f"(c[0]), "+f"(c[1]), "+f"(c[2]), "+f"(c[3])
        : "r"(a[0]), "r"(a[1]), "r"(a[2]), "r"(a[3]), "r"(b[0]), "r"(b[1]));
}

__global__ void __launch_bounds__(NTHREADS, 2)
gather_gemm_tf32(const float* __restrict__ X,
                 const void* __restrict__ ind_raw,
                 const float* __restrict__ W,
                 float* __restrict__ out)
{
    extern __shared__ uint32_t smem[];   // [2 stages][A|B][BM][PITCH]
    __shared__ int sIdx[BM];
    __shared__ int sIs64;

    const int mtile = blockIdx.x;   // 0..7
    const int e     = blockIdx.y;   // 0..15
    const int b     = blockIdx.z;   // 0..3
    const int tid   = threadIdx.x;
    const int lane  = tid & 31;
    const int warp  = tid >> 5;
    const int wm    = warp & 1;     // 0..1
    const int wn    = warp >> 1;    // 0..1

    // ---- dtype sniff: int64 vs int32 indices (values < 4096 -> int64 odd words zero)
    if (warp == 0) {
        const uint32_t* iw = (const uint32_t*)ind_raw;
        uint32_t oddw = iw[2 * lane + 1];
        unsigned mask = __ballot_sync(0xFFFFFFFFu, oddw == 0u);
        if (lane == 0) sIs64 = (mask == 0xFFFFFFFFu) ? 1 : 0;
    }
    __syncthreads();
    const int is64 = sIs64;

    if (tid < BM) {
        size_t p = ((size_t)b * Esz + e) * Csz + (size_t)mtile * BM + tid;
        int t;
        if (is64) t = (int)((const long long*)ind_raw)[p];
        else      t = ((const int*)ind_raw)[p];
        sIdx[tid] = t;
    }
    __syncthreads();

    const float* Xb = X + (size_t)b * Tsz * Isz;
    const float* Wb = W + (size_t)e * Jsz * Isz;

    // global-load assignment: thread covers 8 rows (trow + 16r), one float4 per row
    const int trow = tid >> 3;        // 0..15
    const int tcol = (tid & 7) * 4;   // float col within BK

    const float* aPtr[8];
    const float* bPtr[8];
    uint32_t offA[8], offB[8];        // u32 offsets within a stage
#pragma unroll
    for (int r = 0; r < 8; r++) {
        int m = trow + r * 16;
        aPtr[r] = Xb + (size_t)sIdx[m] * Isz + tcol;
        bPtr[r] = Wb + (size_t)m * Isz + tcol;
        offA[r] = (uint32_t)(m * PITCH + tcol);
        offB[r] = (uint32_t)(TILE_FLOATS + m * PITCH + tcol);
    }

    float acc[4][8][4];
#pragma unroll
    for (int i = 0; i < 4; i++)
#pragma unroll
        for (int j = 0; j < 8; j++)
#pragma unroll
            for (int r = 0; r < 4; r++) acc[i][j][r] = 0.0f;

    const int g = lane >> 2;   // 0..7
    const int q = lane & 3;    // 0..3

    // ---- prologue: tile 0 into registers
    float4 ra[8], rb[8];
#pragma unroll
    for (int r = 0; r < 8; r++) {
        ra[r] = *(const float4*)(aPtr[r]);
        rb[r] = *(const float4*)(bPtr[r]);
    }

    for (int it = 0; it < NITER; it++) {
        uint32_t* stage = smem + (it & 1) * STAGE_FLOATS;

        // store current tile (cvt.rna.tf32 on the way in)
#pragma unroll
        for (int r = 0; r < 8; r++) {
            sts_tf32x4(stage + offA[r], ra[r]);
            sts_tf32x4(stage + offB[r], rb[r]);
        }

        // prefetch next tile into registers (hidden under this iter's compute)
        if (it + 1 < NITER) {
            const int k0 = (it + 1) * BK;
#pragma unroll
            for (int r = 0; r < 8; r++) {
                ra[r] = *(const float4*)(aPtr[r] + k0);
                rb[r] = *(const float4*)(bPtr[r] + k0);
            }
        }

        __syncthreads();

        const uint32_t* cA = stage;
        const uint32_t* cB = stage + TILE_FLOATS;

#pragma unroll
        for (int ks = 0; ks < 4; ks++) {
            const int kk = ks * 8;
            uint32_t areg[4][4];
            uint32_t breg[8][2];
#pragma unroll
            for (int i = 0; i < 4; i++) {
                int m0 = wm * 64 + i * 16;
                areg[i][0] = cA[(m0 + g)     * PITCH + kk + q];
                areg[i][1] = cA[(m0 + g + 8) * PITCH + kk + q];
                areg[i][2] = cA[(m0 + g)     * PITCH + kk + q + 4];
                areg[i][3] = cA[(m0 + g + 8) * PITCH + kk + q + 4];
            }
#pragma unroll
            for (int j = 0; j < 8; j++) {
                int n0 = wn * 64 + j * 8;
                breg[j][0] = cB[(n0 + g) * PITCH + kk + q];
                breg[j][1] = cB[(n0 + g) * PITCH + kk + q + 4];
            }
#pragma unroll
            for (int i = 0; i < 4; i++)
#pragma unroll
                for (int j = 0; j < 8; j++)
                    mma_tf32(acc[i][j], areg[i], breg[j]);
        }
        // NOTE: no second barrier needed — next iter writes the OTHER stage,
        // and the write-after-read hazard on this stage is fenced by the
        // __syncthreads() of the next iteration before it comes back around.
    }

    // ---- epilogue: out[b][e][c][j], BN == J so cols map directly
    float* outp = out + (((size_t)b * Esz + e) * Csz + (size_t)mtile * BM) * Jsz;
#pragma unroll
    for (int i = 0; i < 4; i++) {
        int row0 = wm * 64 + i * 16 + g;
#pragma unroll
        for (int j = 0; j < 8; j++) {
            int col = wn * 64 + j * 8 + 2 * q;
            float2 v0 = make_float2(acc[i][j][0], acc[i][j][1]);
            float2 v1 = make_float2(acc[i][j][2], acc[i][j][3]);
            *(float2*)(outp + (size_t)row0 * Jsz + col)       = v0;
            *(float2*)(outp + (size_t)(row0 + 8) * Jsz + col) = v1;
        }
    }
}

extern "C" void kernel_launch(void* const* d_in, const int* in_sizes, int n_in,
                              void* d_out, int out_size)
{
    const float* X   = (const float*)d_in[0];
    const void*  ind = (const void*)d_in[1];
    const float* W   = (const float*)d_in[2];
    float* out = (float*)d_out;

    cudaFuncSetAttribute(gather_gemm_tf32,
                         cudaFuncAttributeMaxDynamicSharedMemorySize, DYN_SMEM);

    dim3 grid(Csz / BM, Esz, Bsz);   // (8, 16, 4) = 512 CTAs
    dim3 block(NTHREADS);
    gather_gemm_tf32<<<grid, block, DYN_SMEM>>>(X, ind, W, out);
}